// round 1
// baseline (speedup 1.0000x reference)
#include <cuda_runtime.h>
#include <math.h>

// Problem constants
#define N_ATOMS_TOTAL (1024 * 64)   // NCONF * NATOMS
#define NCOEF 21
#define NS 9
#define NAOV 4
#define NSHF 16
#define NPAIR 6
#define OUT_PER_ATOM (NS*NSHF + NAOV*NSHF + NPAIR*NSHF*NSHF)  // 144 + 64 + 1536 = 1744
#define VEC4_PER_ATOM (OUT_PER_ATOM / 4)                      // 436

#define ETA_S 16.0f
#define ETA_R 8.0f
#define ETA_A 8.0f
// shift steps
#define STEP_S (8.0f / 15.0f)   // linspace(-4, 4, 16)
#define STEP_R (4.0f / 15.0f)   // linspace(0, 4, 16)
#define STEP_A (4.0f / 15.0f)   // linspace(0, 4, 16)

__global__ __launch_bounds__(256) void aev_kernel(const float* __restrict__ coeff,
                                                  float* __restrict__ out)
{
    const int atom = blockIdx.x;
    const float* __restrict__ c = coeff + (size_t)atom * NCOEF;
    float* __restrict__ o = out + (size_t)atom * OUT_PER_ATOM;

    __shared__ float sc[NCOEF];
    __shared__ float snorm[NAOV];
    __shared__ float shat[NAOV][3];
    __shared__ float scosp[NPAIR];
    __shared__ float ssinp[NPAIR];
    __shared__ float savd[NPAIR];
    __shared__ float sft[NPAIR][NSHF];   // f_theta
    __shared__ float sfd[NPAIR][NSHF];   // f_dist

    const int tid = threadIdx.x;

    if (tid < NCOEF) sc[tid] = c[tid];
    __syncthreads();

    // Phase 1a: per-vector norms + unit vectors (4 threads)
    if (tid < NAOV) {
        float px = sc[NS + 3*tid + 0];
        float py = sc[NS + 3*tid + 1];
        float pz = sc[NS + 3*tid + 2];
        float n = sqrtf(px*px + py*py + pz*pz);
        snorm[tid] = n;
        bool zm = (fabsf(px) < 1e-12f) && (fabsf(py) < 1e-12f) && (fabsf(pz) < 1e-12f);
        float inv = zm ? 0.0f : (1.0f / n);
        shat[tid][0] = px * inv;
        shat[tid][1] = py * inv;
        shat[tid][2] = pz * inv;
    }
    __syncthreads();

    // Phase 1b: per-pair cos, sin, average distance (6 threads)
    if (tid < NPAIR) {
        const int iu[NPAIR] = {0, 0, 0, 1, 1, 2};
        const int ju[NPAIR] = {1, 2, 3, 2, 3, 3};
        int i = iu[tid], j = ju[tid];
        float cs = shat[i][0]*shat[j][0] + shat[i][1]*shat[j][1] + shat[i][2]*shat[j][2];
        cs = fminf(0.9999f, fmaxf(-0.9999f, cs));
        scosp[tid] = cs;
        ssinp[tid] = sqrtf(fmaxf(0.0f, 1.0f - cs*cs));  // angle in [0,pi] -> sin >= 0
        savd[tid] = (snorm[i] + snorm[j]) * 0.5f;
    }
    __syncthreads();

    // Phase 1c: f_theta (threads 0..95) and f_dist (threads 96..191)
    if (tid < NPAIR * NSHF) {
        int p = tid >> 4;
        int k = tid & 15;
        // theta_k = k * pi / 15 ; cos(angle - theta) = c*cosT + s*sinT
        float st, ct;
        sincospif((float)k * (1.0f / 15.0f), &st, &ct);
        float cosd = scosp[p] * ct + ssinp[p] * st;
        float base = 0.5f * (1.0f + cosd);
        float b2 = base * base;
        float b4 = b2 * b2;
        float b8 = b4 * b4;
        sft[p][k] = b8 * 0.0078125f;   // 2^(1-8)
    } else if (tid < 2 * NPAIR * NSHF) {
        int t = tid - NPAIR * NSHF;
        int p = t >> 4;
        int k = t & 15;
        float d = savd[p] - (float)k * STEP_A;
        sfd[p][k] = __expf(-ETA_A * d * d);
    }
    __syncthreads();

    // Phase 2: write 436 float4 per atom, coalesced
    float4* __restrict__ o4 = reinterpret_cast<float4*>(o);
    for (int f = tid; f < VEC4_PER_ATOM; f += 256) {
        int e = f << 2;
        float4 v;
        if (e < NS * NSHF) {
            // s_aev: si slow, shift fast
            int si = e >> 4;
            int k = e & 15;
            float x = sc[si];
            float d0 = x - (-4.0f + (float)(k + 0) * STEP_S);
            float d1 = x - (-4.0f + (float)(k + 1) * STEP_S);
            float d2 = x - (-4.0f + (float)(k + 2) * STEP_S);
            float d3 = x - (-4.0f + (float)(k + 3) * STEP_S);
            v.x = __expf(-ETA_S * d0 * d0);
            v.y = __expf(-ETA_S * d1 * d1);
            v.z = __expf(-ETA_S * d2 * d2);
            v.w = __expf(-ETA_S * d3 * d3);
        } else if (e < NS * NSHF + NAOV * NSHF) {
            // radial_aev
            int r = e - NS * NSHF;
            int vi = r >> 4;
            int k = r & 15;
            float x = snorm[vi];
            float d0 = x - (float)(k + 0) * STEP_R;
            float d1 = x - (float)(k + 1) * STEP_R;
            float d2 = x - (float)(k + 2) * STEP_R;
            float d3 = x - (float)(k + 3) * STEP_R;
            v.x = __expf(-ETA_R * d0 * d0);
            v.y = __expf(-ETA_R * d1 * d1);
            v.z = __expf(-ETA_R * d2 * d2);
            v.w = __expf(-ETA_R * d3 * d3);
        } else {
            // angular_aev: [pair][theta][dist], dist fastest
            int r = e - (NS * NSHF + NAOV * NSHF);
            int p = r >> 8;          // /256
            int rem = r & 255;
            int i = rem >> 4;
            int j = rem & 15;        // multiple of 4
            float ft = sft[p][i];
            v.x = ft * sfd[p][j + 0];
            v.y = ft * sfd[p][j + 1];
            v.z = ft * sfd[p][j + 2];
            v.w = ft * sfd[p][j + 3];
        }
        o4[f] = v;
    }
}

extern "C" void kernel_launch(void* const* d_in, const int* in_sizes, int n_in,
                              void* d_out, int out_size)
{
    const float* coeff = (const float*)d_in[0];   // [1024, 64, 21] fp32
    // d_in[1] = normalization_library (unused by reference output)
    // d_in[2] = species (unused by reference output)
    float* out = (float*)d_out;                   // [1024, 64, 1744] fp32

    aev_kernel<<<N_ATOMS_TOTAL, 256>>>(coeff, out);
}

// round 3
// speedup vs baseline: 1.1442x; 1.1442x over previous
#include <cuda_runtime.h>
#include <math.h>

#define N_ATOMS_TOTAL (1024 * 64)
#define NCOEF 21
#define OUT_PER_ATOM 1744          // 144 s + 64 radial + 1536 angular
#define EXP_VEC4 52                // (144+64)/4
#define ANG_VEC4 384               // 1536/4
#define STEP_S (8.0f / 15.0f)
#define STEP_R (4.0f / 15.0f)
#define STEP_A (4.0f / 15.0f)

struct HalfSmem {
    float  sc[NCOEF];
    float  snorm[4];
    float  shat[4][3];
    float  scos[8], ssin[8], savd[8];   // padded to 8
    float  sft[96];                     // [pair][theta] flat
    float4 sfd4[24];                    // [pair][dist/4]
};

__global__ __launch_bounds__(256) void aev_kernel(const float* __restrict__ coeff,
                                                  float* __restrict__ out)
{
    __shared__ HalfSmem hs[2];
    const int tid  = threadIdx.x;
    const int half = tid >> 7;          // which atom of the pair
    const int lt   = tid & 127;         // lane within half-block
    HalfSmem& S = hs[half];

    // Persistent grid: each CTA walks atom-pairs
    for (int pairbase = blockIdx.x * 2; pairbase < N_ATOMS_TOTAL;
         pairbase += gridDim.x * 2) {
        const int atom = pairbase + half;
        const float* __restrict__ c = coeff + (size_t)atom * NCOEF;

        // ---- Phase 1: entirely inside warp 0 of each half ----
        if (lt < 32) {
            if (lt < NCOEF) S.sc[lt] = c[lt];
            __syncwarp();
            if (lt < 4) {
                float px = S.sc[9 + 3*lt], py = S.sc[10 + 3*lt], pz = S.sc[11 + 3*lt];
                float n = sqrtf(px*px + py*py + pz*pz);
                S.snorm[lt] = n;
                bool zm = (fabsf(px) < 1e-12f) && (fabsf(py) < 1e-12f) && (fabsf(pz) < 1e-12f);
                float inv = zm ? 0.0f : (1.0f / n);
                S.shat[lt][0] = px * inv;
                S.shat[lt][1] = py * inv;
                S.shat[lt][2] = pz * inv;
            }
            __syncwarp();
            if (lt < 6) {
                const int iu[6] = {0, 0, 0, 1, 1, 2};
                const int ju[6] = {1, 2, 3, 2, 3, 3};
                int i = iu[lt], j = ju[lt];
                float cs = S.shat[i][0]*S.shat[j][0] + S.shat[i][1]*S.shat[j][1]
                         + S.shat[i][2]*S.shat[j][2];
                cs = fminf(0.9999f, fmaxf(-0.9999f, cs));
                S.scos[lt] = cs;
                S.ssin[lt] = sqrtf(fmaxf(0.0f, 1.0f - cs*cs)); // angle in [0,pi]
                S.savd[lt] = (S.snorm[i] + S.snorm[j]) * 0.5f;
            }
        }
        __syncthreads();

        // ---- Phase 1c: 96 threads/half build f_theta and f_dist tables ----
        if (lt < 96) {
            int p = lt >> 4, k = lt & 15;
            float st, ct;
            sincospif((float)k * (1.0f / 15.0f), &st, &ct);     // theta_k = k*pi/15
            float cosd = S.scos[p] * ct + S.ssin[p] * st;        // cos(angle - theta)
            float b  = 0.5f * (1.0f + cosd);
            float b2 = b * b, b4 = b2 * b2;
            S.sft[lt] = b4 * b4 * 0.0078125f;                    // 2^(1-8) * b^8
            float d = S.savd[p] - (float)k * STEP_A;
            reinterpret_cast<float*>(S.sfd4)[lt] = __expf(-8.0f * d * d);
        }
        __syncthreads();

        float4* __restrict__ o4 =
            reinterpret_cast<float4*>(out + (size_t)atom * OUT_PER_ATOM);

        // ---- Angular: exactly 3 branch-free iterations per thread ----
        // element index r = 4f; pair p = f>>6; theta i = (f>>2)&15; dist grp = f&3
        // sft flat idx  = p*16 + i      == f>>2          (exact identity)
        // sfd4 flat idx = p*4  + (f&3)  == ((f>>4)&28) | (f&3)   [5-bit mask!]
        #pragma unroll
        for (int k3 = 0; k3 < 3; k3++) {
            int f = lt + k3 * 128;                 // vec4 index in angular region
            float  ft = S.sft[f >> 2];
            float4 fd = S.sfd4[((f >> 4) & 28) | (f & 3)];
            float4 v  = make_float4(ft*fd.x, ft*fd.y, ft*fd.z, ft*fd.w);
            o4[EXP_VEC4 + f] = v;
        }

        // ---- s + radial: 52 vec4 on warps 2-3 of each half ----
        unsigned t = (unsigned)(lt - 64);
        if (t < EXP_VEC4) {
            float x, base, step, eta;
            if (t < 36) {
                x    = S.sc[t >> 2];
                base = -4.0f + (float)((t & 3) * 4) * STEP_S;
                step = STEP_S; eta = 16.0f;
            } else {
                unsigned r = t - 36;
                x    = S.snorm[r >> 2];
                base = (float)((r & 3) * 4) * STEP_R;
                step = STEP_R; eta = 8.0f;
            }
            float d0 = x - base, d1 = d0 - step, d2 = d1 - step, d3 = d2 - step;
            float4 v = make_float4(__expf(-eta*d0*d0), __expf(-eta*d1*d1),
                                   __expf(-eta*d2*d2), __expf(-eta*d3*d3));
            o4[t] = v;
        }
        __syncthreads();   // protect smem before next atom-pair
    }
}

extern "C" void kernel_launch(void* const* d_in, const int* in_sizes, int n_in,
                              void* d_out, int out_size)
{
    const float* coeff = (const float*)d_in[0];   // [1024, 64, 21] fp32
    float* out = (float*)d_out;                   // [1024, 64, 1744] fp32

    // Persistent grid: ~8 CTAs/SM * 148 SMs
    aev_kernel<<<1184, 256>>>(coeff, out);
}

// round 4
// speedup vs baseline: 1.4483x; 1.2658x over previous
#include <cuda_runtime.h>
#include <math.h>

#define NCOEF 21
#define OUT_PER_ATOM 1744          // 144 s + 64 radial + 1536 angular
#define EXP_VEC4 52                // (144+64)/4
#define WARPS_PER_CTA 16
#define STEP_S (8.0f / 15.0f)
#define STEP_R (4.0f / 15.0f)
#define STEP_A (4.0f / 15.0f)

__global__ __launch_bounds__(512) void aev_kernel(const float* __restrict__ coeff,
                                                  float* __restrict__ out)
{
    // Per-warp private smem slices (no cross-warp sharing -> only __syncwarp needed)
    __shared__ float  s_ft[WARPS_PER_CTA][96];   // f_theta [pair*16 + k]
    __shared__ float4 s_fd[WARPS_PER_CTA][24];   // f_dist  [pair*4 + j4]
    __shared__ float  s_sn[WARPS_PER_CTA][16];   // [0..8]=s_coeffs, [9..12]=norms

    const int lane = threadIdx.x & 31;
    const int wid  = threadIdx.x >> 5;
    const int atom = blockIdx.x * WARPS_PER_CTA + wid;

    const float* __restrict__ c = coeff + (size_t)atom * NCOEF;

    // Lane i<21 loads coefficient i; broadcast via shfl (warp fully converged here)
    float cval = (lane < NCOEF) ? __ldg(c + lane) : 0.0f;

    float p[12];
    #pragma unroll
    for (int i = 0; i < 12; i++)
        p[i] = __shfl_sync(0xffffffffu, cval, 9 + i);

    // Every lane redundantly computes norms + unit vectors (registers only)
    float n[4], hx[4], hy[4], hz[4];
    #pragma unroll
    for (int q = 0; q < 4; q++) {
        float px = p[3*q], py = p[3*q+1], pz = p[3*q+2];
        float nn = sqrtf(px*px + py*py + pz*pz);
        n[q] = nn;
        bool zm = (fabsf(px) < 1e-12f) && (fabsf(py) < 1e-12f) && (fabsf(pz) < 1e-12f);
        float inv = zm ? 0.0f : (1.0f / nn);
        hx[q] = px * inv; hy[q] = py * inv; hz[q] = pz * inv;
    }

    // 6 pairs: cos, sin (angle in [0,pi] -> sin >= 0), average distance
    float pcos[6], psin[6], pavd[6];
    {
        const int iu[6] = {0, 0, 0, 1, 1, 2};
        const int ju[6] = {1, 2, 3, 2, 3, 3};
        #pragma unroll
        for (int e = 0; e < 6; e++) {
            int i = iu[e], j = ju[e];
            float cs = hx[i]*hx[j] + hy[i]*hy[j] + hz[i]*hz[j];
            cs = fminf(0.9999f, fmaxf(-0.9999f, cs));
            pcos[e] = cs;
            psin[e] = sqrtf(fmaxf(0.0f, 1.0f - cs*cs));
            pavd[e] = (n[i] + n[j]) * 0.5f;
        }
    }

    // Stage s_coeffs + norms to smem (avoids dynamic register indexing later)
    if (lane < 9)                  s_sn[wid][lane] = cval;
    else if (lane < 13)            s_sn[wid][lane] = n[lane - 9];

    // Build f_theta / f_dist tables: 3 rounds x 32 lanes = 96 entries
    #pragma unroll
    for (int r = 0; r < 3; r++) {
        int idx = lane + 32*r;
        int pp = idx >> 4, k = idx & 15;
        float st, ct;
        sincospif((float)k * (1.0f / 15.0f), &st, &ct);     // theta_k = k*pi/15
        float cosd = pcos[pp]*ct + psin[pp]*st;              // cos(angle - theta_k)
        float b  = 0.5f * (1.0f + cosd);
        float b2 = b*b, b4 = b2*b2;
        s_ft[wid][idx] = b4 * b4 * 0.0078125f;               // 2^(1-8) * b^8
        float d = pavd[pp] - (float)k * STEP_A;
        reinterpret_cast<float*>(s_fd[wid])[idx] = __expf(-8.0f * d * d);
    }
    __syncwarp();

    float4* __restrict__ o4 =
        reinterpret_cast<float4*>(out + (size_t)atom * OUT_PER_ATOM);

    // Angular region: 384 vec4, 12 branch-free rounds, fully coalesced (512B/warp/round)
    // f: vec4 idx; pair = f>>6; sft idx = f>>2; sfd idx = pair*4+(f&3) = ((f>>4)&28)|(f&3)
    #pragma unroll
    for (int r = 0; r < 12; r++) {
        int f = lane + 32*r;
        float  ft = s_ft[wid][f >> 2];
        float4 fd = s_fd[wid][((f >> 4) & 28) | (f & 3)];
        float4 v  = make_float4(ft*fd.x, ft*fd.y, ft*fd.z, ft*fd.w);
        __stcs(&o4[EXP_VEC4 + f], v);
    }

    // s + radial regions: 52 vec4 in 2 rounds
    #pragma unroll
    for (int r = 0; r < 2; r++) {
        int t = lane + 32*r;
        if (t < EXP_VEC4) {
            bool isS = t < 36;
            int  q   = isS ? (t >> 2) : (9 + ((t - 36) >> 2));
            float x    = s_sn[wid][q];
            // 36 % 4 == 0, so (t-36)&3 == t&3 in the radial branch
            float base = isS ? (-4.0f + (float)((t & 3) * 4) * STEP_S)
                             : ((float)((t & 3) * 4) * STEP_R);
            float step = isS ? STEP_S : STEP_R;
            float eta  = isS ? 16.0f : 8.0f;
            float d0 = x - base, d1 = d0 - step, d2 = d1 - step, d3 = d2 - step;
            float4 v = make_float4(__expf(-eta*d0*d0), __expf(-eta*d1*d1),
                                   __expf(-eta*d2*d2), __expf(-eta*d3*d3));
            __stcs(&o4[t], v);
        }
    }
}

extern "C" void kernel_launch(void* const* d_in, const int* in_sizes, int n_in,
                              void* d_out, int out_size)
{
    const float* coeff = (const float*)d_in[0];   // [1024, 64, 21] fp32
    float* out = (float*)d_out;                   // [1024, 64, 1744] fp32

    // one warp per atom: 65536 atoms / 16 warps per CTA
    aev_kernel<<<65536 / WARPS_PER_CTA, 32 * WARPS_PER_CTA>>>(coeff, out);
}

// round 5
// speedup vs baseline: 1.7476x; 1.2066x over previous
#include <cuda_runtime.h>
#include <math.h>

#define NCOEF 21
#define OUT_PER_ATOM 1744          // 144 s + 64 radial + 1536 angular
#define EXP_VEC4 52                // (144+64)/4
#define WARPS_PER_CTA 8
#define STEP_S (8.0f / 15.0f)
#define STEP_R (4.0f / 15.0f)
#define STEP_A (4.0f / 15.0f)

__global__ __launch_bounds__(256, 5) void aev_kernel(const float* __restrict__ coeff,
                                                     float* __restrict__ out)
{
    // Per-warp private smem (only __syncwarp needed)
    __shared__ float4 s_fd[WARPS_PER_CTA][24];   // f_dist  [pair*4 + j4]
    __shared__ float  s_sn[WARPS_PER_CTA][16];   // [0..8]=s_coeffs, [9..12]=norms

    const int lane = threadIdx.x & 31;
    const int wid  = threadIdx.x >> 5;
    const int atom = blockIdx.x * WARPS_PER_CTA + wid;

    const float* __restrict__ c = coeff + (size_t)atom * NCOEF;

    // Lane i<21 loads coefficient i; broadcast via shfl
    float cval = (lane < NCOEF) ? __ldg(c + lane) : 0.0f;

    float p[12];
    #pragma unroll
    for (int i = 0; i < 12; i++)
        p[i] = __shfl_sync(0xffffffffu, cval, 9 + i);

    // Every lane redundantly computes norms + unit vectors
    float n[4], hx[4], hy[4], hz[4];
    #pragma unroll
    for (int q = 0; q < 4; q++) {
        float px = p[3*q], py = p[3*q+1], pz = p[3*q+2];
        float nn = sqrtf(px*px + py*py + pz*pz);
        n[q] = nn;
        bool zm = (fabsf(px) < 1e-12f) && (fabsf(py) < 1e-12f) && (fabsf(pz) < 1e-12f);
        float inv = zm ? 0.0f : (1.0f / nn);
        hx[q] = px * inv; hy[q] = py * inv; hz[q] = pz * inv;
    }

    // 6 pairs: cos, sin (angle in [0,pi] -> sin >= 0), average distance
    float pcos[6], psin[6], pavd[6];
    {
        const int iu[6] = {0, 0, 0, 1, 1, 2};
        const int ju[6] = {1, 2, 3, 2, 3, 3};
        #pragma unroll
        for (int e = 0; e < 6; e++) {
            int i = iu[e], j = ju[e];
            float cs = hx[i]*hx[j] + hy[i]*hy[j] + hz[i]*hz[j];
            cs = fminf(0.9999f, fmaxf(-0.9999f, cs));
            pcos[e] = cs;
            psin[e] = sqrtf(fmaxf(0.0f, 1.0f - cs*cs));
            pavd[e] = (n[i] + n[j]) * 0.5f;
        }
    }

    // Stage s_coeffs + norms for the exp region
    if (lane < 9)        s_sn[wid][lane] = cval;
    else if (lane < 13)  s_sn[wid][lane] = n[lane - 9];

    // ---- Table build: idx = lane + 32t; k = idx&15 = lane&15 (lane-invariant
    // across rounds!); p = idx>>4 = (lane>>4) + 2t (select between 2 regs).
    const int k = lane & 15;
    const bool hi = (lane & 16) != 0;
    float st, ct;
    sincospif((float)k * (1.0f / 15.0f), &st, &ct);    // theta_k = k*pi/15
    const float kstep = (float)k * STEP_A;

    float ft_reg[3];                                    // lane owns ft[lane+32t]
    #pragma unroll
    for (int t = 0; t < 3; t++) {
        float cs = hi ? pcos[2*t+1] : pcos[2*t];
        float sn = hi ? psin[2*t+1] : psin[2*t];
        float av = hi ? pavd[2*t+1] : pavd[2*t];
        float cosd = cs * ct + sn * st;                 // cos(angle - theta_k)
        float b  = 0.5f * (1.0f + cosd);
        float b2 = b*b, b4 = b2*b2;
        ft_reg[t] = b4 * b4 * 0.0078125f;               // 2^(1-8) * b^8
        float d = av - kstep;
        reinterpret_cast<float*>(s_fd[wid])[lane + 32*t] = __expf(-8.0f * d * d);
    }
    __syncwarp();

    // Pre-load this lane's 6 f_dist float4s (pair p, dist group lane&3)
    float4 fd_regs[6];
    #pragma unroll
    for (int pp = 0; pp < 6; pp++)
        fd_regs[pp] = s_fd[wid][pp*4 + (lane & 3)];

    float4* __restrict__ o4 =
        reinterpret_cast<float4*>(out + (size_t)atom * OUT_PER_ATOM);

    // ---- Angular: 12 rounds, register-fed. f = lane+32r:
    //   pair     = f>>6 = r>>1            (uniform per round)
    //   ft index = f>>2 = 8r + (lane>>2)  -> shfl from owning lane
    //   fd       = fd_regs[r>>1]          (this lane's dist group)
    #pragma unroll
    for (int r = 0; r < 12; r++) {
        float ft = __shfl_sync(0xffffffffu, ft_reg[r >> 2],
                               ((r & 3) << 3) + (lane >> 2));
        float4 fd = fd_regs[r >> 1];
        float4 v  = make_float4(ft*fd.x, ft*fd.y, ft*fd.z, ft*fd.w);
        __stcs(&o4[EXP_VEC4 + (lane + 32*r)], v);
    }

    // ---- s + radial regions: 52 vec4 in 2 rounds
    #pragma unroll
    for (int r = 0; r < 2; r++) {
        int t = lane + 32*r;
        if (t < EXP_VEC4) {
            bool isS = t < 36;
            int  q   = isS ? (t >> 2) : (9 + ((t - 36) >> 2));
            float x    = s_sn[wid][q];
            float base = isS ? (-4.0f + (float)((t & 3) * 4) * STEP_S)
                             : ((float)((t & 3) * 4) * STEP_R);
            float step = isS ? STEP_S : STEP_R;
            float eta  = isS ? 16.0f : 8.0f;
            float d0 = x - base, d1 = d0 - step, d2 = d1 - step, d3 = d2 - step;
            float4 v = make_float4(__expf(-eta*d0*d0), __expf(-eta*d1*d1),
                                   __expf(-eta*d2*d2), __expf(-eta*d3*d3));
            __stcs(&o4[t], v);
        }
    }
}

extern "C" void kernel_launch(void* const* d_in, const int* in_sizes, int n_in,
                              void* d_out, int out_size)
{
    const float* coeff = (const float*)d_in[0];   // [1024, 64, 21] fp32
    float* out = (float*)d_out;                   // [1024, 64, 1744] fp32

    // one warp per atom: 65536 atoms / 8 warps per CTA
    aev_kernel<<<65536 / WARPS_PER_CTA, 32 * WARPS_PER_CTA>>>(coeff, out);
}